// round 8
// baseline (speedup 1.0000x reference)
#include <cuda_runtime.h>
#include <cuda_fp16.h>
#include <cstdint>

#define B_  4
#define T_  2048
#define E_  512
#define H_  8
#define HS_ 64
#define NH  (H_ * HS_)   // 512

// ---------------- scratch (device globals; no allocation allowed) ----------
__device__ __half g_xh[(size_t)B_ * T_ * E_];        // fp16 x
__device__ __half g_wqkvh[3 * NH * E_];              // K-major [w*512+h*64+d][e]
__device__ __half g_wpTh[E_ * NH];                   // K-major [n][k]
__device__ __half g_qh[(size_t)B_ * H_ * T_ * HS_];  // [B,H,T,HS]
__device__ __half g_kh[(size_t)B_ * H_ * T_ * HS_];  // [B,H,T,HS]
__device__ __half g_vT[(size_t)B_ * H_ * HS_ * T_];  // [B,H,HS,T]  (transposed)
__device__ __half g_oh[(size_t)B_ * T_ * NH];        // [B,T,H*HS]

// ======================= helpers ===========================================
__device__ __forceinline__ uint32_t smem_u32(const void* p) {
    uint32_t a;
    asm("{ .reg .u64 t; cvta.to.shared.u64 t, %1; cvt.u32.u64 %0, t; }"
        : "=r"(a) : "l"(p));
    return a;
}
// D += A(16x16 f16 row) * B(16x8 f16 col)
__device__ __forceinline__ void mma16(float d[4], const uint32_t a[4],
                                      const uint32_t b[2]) {
    asm volatile(
        "mma.sync.aligned.m16n8k16.row.col.f32.f16.f16.f32 "
        "{%0,%1,%2,%3},{%4,%5,%6,%7},{%8,%9},{%0,%1,%2,%3};"
        : "+f"(d[0]), "+f"(d[1]), "+f"(d[2]), "+f"(d[3])
        : "r"(a[0]), "r"(a[1]), "r"(a[2]), "r"(a[3]), "r"(b[0]), "r"(b[1]));
}
#define LDSM4(r0, r1, r2, r3, addr)                                          \
    asm volatile("ldmatrix.sync.aligned.m8n8.x4.shared.b16 "                 \
                 "{%0,%1,%2,%3}, [%4];"                                      \
                 : "=r"(r0), "=r"(r1), "=r"(r2), "=r"(r3) : "r"(addr))
#define CP16(ds, sp)  asm volatile("cp.async.cg.shared.global [%0], [%1], 16;" :: "r"(ds), "l"(sp))
#define CPCOMMIT()    asm volatile("cp.async.commit_group;" ::: "memory")
#define CPWAIT0()     asm volatile("cp.async.wait_group 0;" ::: "memory")

// ======================= prep kernels ======================================
__global__ __launch_bounds__(256)
void conv_x(const float* __restrict__ x)
{
    size_t i = ((size_t)blockIdx.x * 256 + threadIdx.x) * 8;
    float4 v0 = *(const float4*)(x + i);
    float4 v1 = *(const float4*)(x + i + 4);
    __half2 h[4];
    h[0] = __floats2half2_rn(v0.x, v0.y);
    h[1] = __floats2half2_rn(v0.z, v0.w);
    h[2] = __floats2half2_rn(v1.x, v1.y);
    h[3] = __floats2half2_rn(v1.z, v1.w);
    *(uint4*)(g_xh + i) = *(uint4*)h;
}

// g_wqkvh[(w*512 + h*64 + d)][e] = w_src[h][e][d]
__global__ __launch_bounds__(256)
void tr_wqkv(const float* __restrict__ wq, const float* __restrict__ wk,
             const float* __restrict__ wv)
{
    __shared__ float tt[64][65];
    const int w = blockIdx.z, h = blockIdx.y, e0 = blockIdx.x * 64;
    const float* src = (w == 0 ? wq : (w == 1 ? wk : wv)) + (size_t)h * E_ * HS_;
    const int tid = threadIdx.x;
    #pragma unroll
    for (int r = 0; r < 16; r++) {
        int idx = tid + r * 256, e = idx >> 6, d = idx & 63;
        tt[e][d] = src[(size_t)(e0 + e) * HS_ + d];
    }
    __syncthreads();
    __half* dst = g_wqkvh + (size_t)(w * 512 + h * 64) * E_;
    #pragma unroll
    for (int r = 0; r < 16; r++) {
        int idx = tid + r * 256, d = idx >> 6, e = idx & 63;
        dst[(size_t)d * E_ + e0 + e] = __float2half_rn(tt[e][d]);
    }
}

// g_wpTh[n][k] = wp[k][n]
__global__ __launch_bounds__(256)
void tr_wp(const float* __restrict__ wp)
{
    __shared__ float tt[64][65];
    const int k0 = blockIdx.x * 64, n0 = blockIdx.y * 64;
    const int tid = threadIdx.x;
    #pragma unroll
    for (int r = 0; r < 16; r++) {
        int idx = tid + r * 256, k = idx >> 6, n = idx & 63;
        tt[k][n] = wp[(size_t)(k0 + k) * E_ + n0 + n];
    }
    __syncthreads();
    #pragma unroll
    for (int r = 0; r < 16; r++) {
        int idx = tid + r * 256, n = idx >> 6, k = idx & 63;
        g_wpTh[(size_t)(n0 + n) * NH + k0 + k] = __float2half_rn(tt[k][n]);
    }
}

// ======================= GEMM core (fp16 mma.sync + ldmatrix) ==============
// 128 threads = 4 warps in 2x2. Block tile 128x128, warp tile 64x64.
// K chunks of 64 halves (4 k16-steps), cp.async 2-stage. Rows padded to
// 144 B: ldmatrix row set hits banks 0,4,...,28 -> conflict-free.
#define GEMM_STG_B  36864                  // 256 rows * 144 B
#define GEMM_SMEM   (2 * GEMM_STG_B)       // 73728 B

__device__ __forceinline__ void gemm_issue(uint32_t sb, int st, int c,
                                           const __half* __restrict__ Ag,
                                           const __half* __restrict__ Bg,
                                           int m0, int n0)
{
    const int tid = threadIdx.x;
    uint32_t as_ = sb + (uint32_t)st * GEMM_STG_B;
    uint32_t bs_ = as_ + 128 * 144;
    #pragma unroll
    for (int i = 0; i < 8; i++) {
        int idx = tid + i * 128, row = idx >> 3, f4 = idx & 7;
        CP16(as_ + (uint32_t)(row * 144 + f4 * 16),
             Ag + (size_t)(m0 + row) * 512 + c * 64 + f4 * 8);
    }
    #pragma unroll
    for (int i = 0; i < 8; i++) {
        int idx = tid + i * 128, row = idx >> 3, f4 = idx & 7;
        CP16(bs_ + (uint32_t)(row * 144 + f4 * 16),
             Bg + (size_t)(n0 + row) * 512 + c * 64 + f4 * 8);
    }
    CPCOMMIT();
}

__device__ __forceinline__ void gemm_core(const __half* __restrict__ Ag,
                                          const __half* __restrict__ Bg,
                                          float acc[4][8][4])
{
    extern __shared__ char gsm[];
    const uint32_t sb = smem_u32(gsm);
    const int tid = threadIdx.x;
    const int m0 = blockIdx.x * 128, n0 = blockIdx.y * 128;
    const int wid = tid >> 5, wm = wid >> 1, wn = wid & 1;
    const int lane = tid & 31;
    const int lrow = lane & 15, lcol = (lane >> 4) << 4;

    // lane-invariant ldmatrix address components
    uint32_t arow[4], brow[4];
    #pragma unroll
    for (int mt = 0; mt < 4; mt++)
        arow[mt] = (uint32_t)((wm * 64 + mt * 16 + lrow) * 144 + lcol);
    #pragma unroll
    for (int np = 0; np < 4; np++)
        brow[np] = (uint32_t)(128 * 144 + (wn * 64 + np * 16 + lrow) * 144 + lcol);

    gemm_issue(sb, 0, 0, Ag, Bg, m0, n0);

    for (int c = 0; c < 8; c++) {
        CPWAIT0();
        __syncthreads();
        if (c < 7) gemm_issue(sb, (c + 1) & 1, c + 1, Ag, Bg, m0, n0);

        const uint32_t stg = sb + (uint32_t)(c & 1) * GEMM_STG_B;

        uint32_t a[2][4][4], bb[2][8][2];
        auto ldf = [&](int ks, int sl) {
            #pragma unroll
            for (int mt = 0; mt < 4; mt++)
                LDSM4(a[sl][mt][0], a[sl][mt][1], a[sl][mt][2], a[sl][mt][3],
                      stg + arow[mt] + ks * 32);
            #pragma unroll
            for (int np = 0; np < 4; np++)
                LDSM4(bb[sl][2 * np][0], bb[sl][2 * np + 1][0],
                      bb[sl][2 * np][1], bb[sl][2 * np + 1][1],
                      stg + brow[np] + ks * 32);
        };
        ldf(0, 0);
        #pragma unroll
        for (int ks = 0; ks < 4; ks++) {
            int cur = ks & 1;
            if (ks < 3) ldf(ks + 1, cur ^ 1);
            #pragma unroll
            for (int mt = 0; mt < 4; mt++)
                #pragma unroll
                for (int nt = 0; nt < 8; nt++)
                    mma16(acc[mt][nt], a[cur][mt], bb[cur][nt]);
        }
    }
}

// qkv: C[8192,1536] = g_xh @ g_wqkvh^T; scatter to g_qh/g_kh/g_vT
__global__ __launch_bounds__(128)
void qkv_gemm()
{
    float acc[4][8][4] = {};
    gemm_core(g_xh, g_wqkvh, acc);

    const int tid = threadIdx.x;
    const int wid = tid >> 5, wm = wid >> 1, wn = wid & 1;
    const int lane = tid & 31, g = lane >> 2, t = lane & 3;
    const int m0 = blockIdx.x * 128, n0 = blockIdx.y * 128;

    #pragma unroll
    for (int nt = 0; nt < 8; nt++) {
        int nb = n0 + wn * 64 + nt * 8;
        int w = nb >> 9, h = (nb >> 6) & 7, d = (nb & 63) + 2 * t;
        #pragma unroll
        for (int mt = 0; mt < 4; mt++) {
            int m = m0 + wm * 64 + mt * 16 + g;
            int b = m >> 11, tt = m & 2047;
            if (w < 2) {   // Q, K : [B,H,T,HS]
                __half* dst = (w == 0 ? g_qh : g_kh);
                size_t base = ((size_t)(b * H_ + h) * T_ + tt) * HS_ + d;
                *(half2*)(dst + base) =
                    __floats2half2_rn(acc[mt][nt][0], acc[mt][nt][1]);
                *(half2*)(dst + base + 8 * HS_) =
                    __floats2half2_rn(acc[mt][nt][2], acc[mt][nt][3]);
            } else {       // V : transposed [B,H,HS,T]
                size_t base = ((size_t)(b * H_ + h) * HS_ + d) * T_ + tt;
                g_vT[base]          = __float2half_rn(acc[mt][nt][0]);
                g_vT[base + T_]     = __float2half_rn(acc[mt][nt][1]);
                g_vT[base + 8]      = __float2half_rn(acc[mt][nt][2]);
                g_vT[base + T_ + 8] = __float2half_rn(acc[mt][nt][3]);
            }
        }
    }
}

// proj: out[8192,512] = g_oh @ wp (via K-major g_wpTh)
__global__ __launch_bounds__(128)
void proj_gemm(float* __restrict__ out)
{
    float acc[4][8][4] = {};
    gemm_core(g_oh, g_wpTh, acc);

    const int tid = threadIdx.x;
    const int wid = tid >> 5, wm = wid >> 1, wn = wid & 1;
    const int lane = tid & 31, g = lane >> 2, t = lane & 3;
    const int m0 = blockIdx.x * 128, n0 = blockIdx.y * 128;

    #pragma unroll
    for (int nt = 0; nt < 8; nt++) {
        int n = n0 + wn * 64 + nt * 8 + 2 * t;
        #pragma unroll
        for (int mt = 0; mt < 4; mt++) {
            int m = m0 + wm * 64 + mt * 16 + g;
            float2 v0 = { acc[mt][nt][0], acc[mt][nt][1] };
            float2 v1 = { acc[mt][nt][2], acc[mt][nt][3] };
            *(float2*)(out + (size_t)m * E_ + n)       = v0;
            *(float2*)(out + (size_t)(m + 8) * E_ + n) = v1;
        }
    }
}

// ======================= flash attention (fp16 mma + ldmatrix) =============
// 128 threads = 4 warps. Q tile 128 rows, warp = 32 rows (2 m16 sub-tiles).
// K/V(transposed) 64-key tiles, cp.async double-buffered. 144 B rows.
#define AKB(buf)  ((uint32_t)(buf) * 9216)            // K: 64 rows * 144 B
#define AVB(buf)  (18432u + (uint32_t)(buf) * 9216)   // Vt: 64 rows * 144 B
#define APB       36864u                              // P/Q: 128 rows * 144 B
#define ATT_SMEM  (36864 + 128 * 144)                 // 55296 B

__device__ __forceinline__ void attn_stage(uint32_t sb,
                                           const __half* __restrict__ kp,
                                           const __half* __restrict__ vtp,
                                           int n0, int buf)
{
    const int tid = threadIdx.x;
    uint32_t kb = sb + AKB(buf);
    uint32_t vb = sb + AVB(buf);
    #pragma unroll
    for (int i = 0; i < 4; i++) {
        int idx = tid + i * 128, row = idx >> 3, f4 = idx & 7;
        CP16(kb + (uint32_t)(row * 144 + f4 * 16),
             kp + (size_t)(n0 + row) * HS_ + f4 * 8);
        CP16(vb + (uint32_t)(row * 144 + f4 * 16),
             vtp + (size_t)row * T_ + n0 + f4 * 8);
    }
    CPCOMMIT();
}

__global__ __launch_bounds__(128)
void attn_tc()
{
    extern __shared__ char asmem[];
    const uint32_t sb = smem_u32(asmem);

    const int b = blockIdx.z, h = blockIdx.y;
    const int qt = (T_ / 128) - 1 - blockIdx.x;   // heavy tiles first
    const int m0 = qt * 128;
    const int tid = threadIdx.x, wid = tid >> 5, lane = tid & 31;
    const int g = lane >> 2, t = lane & 3;
    const int lrow = lane & 15, lcol = (lane >> 4) << 4;
    const int mrow = wid * 32;
    const int ktmax = m0 / 64 + 2;

    const __half* qp  = g_qh + (size_t)(b * H_ + h) * T_ * HS_;
    const __half* kp  = g_kh + (size_t)(b * H_ + h) * T_ * HS_;
    const __half* vtp = g_vT + (size_t)(b * H_ + h) * HS_ * T_;

    attn_stage(sb, kp, vtp, 0, 0);

    // lane-invariant ldmatrix address components
    uint32_t prow[2], nrow[4];
    #pragma unroll
    for (int ms = 0; ms < 2; ms++)
        prow[ms] = sb + APB + (uint32_t)((mrow + ms * 16 + lrow) * 144 + lcol);
    #pragma unroll
    for (int np = 0; np < 4; np++)
        nrow[np] = (uint32_t)((np * 16 + lrow) * 144 + lcol);

    // stage this warp's 32 Q rows into its P-slice via cp.async
    {
        uint32_t pb = sb + APB + (uint32_t)(mrow * 144);
        #pragma unroll
        for (int i = 0; i < 8; i++) {
            int idx = lane + i * 32, row = idx >> 3, f4 = idx & 7;
            CP16(pb + (uint32_t)(row * 144 + f4 * 16),
                 qp + (size_t)(m0 + mrow + row) * HS_ + f4 * 8);
        }
        CPCOMMIT();
        CPWAIT0();
        __syncwarp();
    }
    uint32_t q[2][4][4];
    #pragma unroll
    for (int ms = 0; ms < 2; ms++)
        #pragma unroll
        for (int ks = 0; ks < 4; ks++)
            LDSM4(q[ms][ks][0], q[ms][ks][1], q[ms][ks][2], q[ms][ks][3],
                  prow[ms] + ks * 32);

    float o[2][8][4] = {};
    float mrA[2] = {-1e30f, -1e30f}, mrB[2] = {-1e30f, -1e30f};
    float lA[2] = {}, lB[2] = {};

    for (int kt = 0; kt < ktmax; kt++) {
        CPWAIT0();
        __syncthreads();
        if (kt + 1 < ktmax) attn_stage(sb, kp, vtp, (kt + 1) * 64, (kt + 1) & 1);

        const int n0 = kt * 64;
        const int buf = kt & 1;
        if (n0 <= m0 + mrow + 31) {
            const uint32_t kbase = sb + AKB(buf);
            const uint32_t vbase = sb + AVB(buf);

            // S = Q K^T
            float s[2][8][4] = {};
            #pragma unroll
            for (int ks = 0; ks < 4; ks++) {
                uint32_t kb[8][2];
                #pragma unroll
                for (int np = 0; np < 4; np++)
                    LDSM4(kb[2 * np][0], kb[2 * np + 1][0],
                          kb[2 * np][1], kb[2 * np + 1][1],
                          kbase + nrow[np] + ks * 32);
                #pragma unroll
                for (int nt = 0; nt < 8; nt++) {
                    mma16(s[0][nt], q[0][ks], kb[nt]);
                    mma16(s[1][nt], q[1][ks], kb[nt]);
                }
            }

            const float sc = 0.125f;   // 1/sqrt(64)
            #pragma unroll
            for (int ms = 0; ms < 2; ms++)
                #pragma unroll
                for (int nt = 0; nt < 8; nt++) {
                    s[ms][nt][0] *= sc; s[ms][nt][1] *= sc;
                    s[ms][nt][2] *= sc; s[ms][nt][3] *= sc;
                }
            if (n0 + 63 > m0 + mrow) {   // diagonal region: causal mask
                #pragma unroll
                for (int ms = 0; ms < 2; ms++) {
                    int rA = m0 + mrow + ms * 16 + g, rB = rA + 8;
                    #pragma unroll
                    for (int nt = 0; nt < 8; nt++) {
                        int c0 = n0 + nt * 8 + 2 * t, c1 = c0 + 1;
                        if (c0 > rA) s[ms][nt][0] = -1e30f;
                        if (c1 > rA) s[ms][nt][1] = -1e30f;
                        if (c0 > rB) s[ms][nt][2] = -1e30f;
                        if (c1 > rB) s[ms][nt][3] = -1e30f;
                    }
                }
            }

            // online softmax per m-subtile
            #pragma unroll
            for (int ms = 0; ms < 2; ms++) {
                float mx0 = -1e30f, mx1 = -1e30f;
                #pragma unroll
                for (int nt = 0; nt < 8; nt++) {
                    mx0 = fmaxf(mx0, fmaxf(s[ms][nt][0], s[ms][nt][1]));
                    mx1 = fmaxf(mx1, fmaxf(s[ms][nt][2], s[ms][nt][3]));
                }
                mx0 = fmaxf(mx0, __shfl_xor_sync(0xffffffffu, mx0, 1));
                mx0 = fmaxf(mx0, __shfl_xor_sync(0xffffffffu, mx0, 2));
                mx1 = fmaxf(mx1, __shfl_xor_sync(0xffffffffu, mx1, 1));
                mx1 = fmaxf(mx1, __shfl_xor_sync(0xffffffffu, mx1, 2));
                float mn0 = fmaxf(mrA[ms], mx0), mn1 = fmaxf(mrB[ms], mx1);
                float al0 = __expf(mrA[ms] - mn0), al1 = __expf(mrB[ms] - mn1);
                mrA[ms] = mn0; mrB[ms] = mn1;

                float su0 = 0.0f, su1 = 0.0f;
                #pragma unroll
                for (int nt = 0; nt < 8; nt++) {
                    s[ms][nt][0] = __expf(s[ms][nt][0] - mn0);
                    s[ms][nt][1] = __expf(s[ms][nt][1] - mn0);
                    s[ms][nt][2] = __expf(s[ms][nt][2] - mn1);
                    s[ms][nt][3] = __expf(s[ms][nt][3] - mn1);
                    su0 += s[ms][nt][0] + s[ms][nt][1];
                    su1 += s[ms][nt][2] + s[ms][nt][3];
                }
                su0 += __shfl_xor_sync(0xffffffffu, su0, 1);
                su0 += __shfl_xor_sync(0xffffffffu, su0, 2);
                su1 += __shfl_xor_sync(0xffffffffu, su1, 1);
                su1 += __shfl_xor_sync(0xffffffffu, su1, 2);
                lA[ms] = lA[ms] * al0 + su0;
                lB[ms] = lB[ms] * al1 + su1;

                #pragma unroll
                for (int nt = 0; nt < 8; nt++) {
                    o[ms][nt][0] *= al0; o[ms][nt][1] *= al0;
                    o[ms][nt][2] *= al1; o[ms][nt][3] *= al1;
                }
            }

            // stage P (fp16) into this warp's P-slice
            __syncwarp();
            #pragma unroll
            for (int ms = 0; ms < 2; ms++) {
                char* r0 = asmem + APB + (mrow + ms * 16 + g) * 144;
                char* r1 = asmem + APB + (mrow + ms * 16 + g + 8) * 144;
                #pragma unroll
                for (int nt = 0; nt < 8; nt++) {
                    *(half2*)(r0 + (nt * 8 + 2 * t) * 2) =
                        __floats2half2_rn(s[ms][nt][0], s[ms][nt][1]);
                    *(half2*)(r1 + (nt * 8 + 2 * t) * 2) =
                        __floats2half2_rn(s[ms][nt][2], s[ms][nt][3]);
                }
            }
            __syncwarp();

            // O += P V  (A = P over keys, B = Vt fragments)
            #pragma unroll
            for (int ks = 0; ks < 4; ks++) {
                uint32_t pa[2][4], bv[8][2];
                #pragma unroll
                for (int ms = 0; ms < 2; ms++)
                    LDSM4(pa[ms][0], pa[ms][1], pa[ms][2], pa[ms][3],
                          prow[ms] + ks * 32);
                #pragma unroll
                for (int np = 0; np < 4; np++)
                    LDSM4(bv[2 * np][0], bv[2 * np + 1][0],
                          bv[2 * np][1], bv[2 * np + 1][1],
                          vbase + nrow[np] + ks * 32);
                #pragma unroll
                for (int nt = 0; nt < 8; nt++) {
                    mma16(o[0][nt], pa[0], bv[nt]);
                    mma16(o[1][nt], pa[1], bv[nt]);
                }
            }
        }
    }

    // epilogue: normalize, write fp16 O in [B,T,H*HS]
    __half* op = g_oh + ((size_t)b * T_ + m0 + mrow) * NH + h * HS_;
    #pragma unroll
    for (int ms = 0; ms < 2; ms++) {
        float iA = 1.0f / lA[ms], iB = 1.0f / lB[ms];
        int rr = ms * 16 + g;
        #pragma unroll
        for (int nt = 0; nt < 8; nt++) {
            int c = nt * 8 + 2 * t;
            *(half2*)&op[(size_t)rr * NH + c] =
                __floats2half2_rn(o[ms][nt][0] * iA, o[ms][nt][1] * iA);
            *(half2*)&op[(size_t)(rr + 8) * NH + c] =
                __floats2half2_rn(o[ms][nt][2] * iB, o[ms][nt][3] * iB);
        }
    }
}

// ---------------------------------------------------------------------------
extern "C" void kernel_launch(void* const* d_in, const int* in_sizes, int n_in,
                              void* d_out, int out_size)
{
    const float* x  = (const float*)d_in[0];
    const float* wq = (const float*)d_in[1];
    const float* wk = (const float*)d_in[2];
    const float* wv = (const float*)d_in[3];
    const float* wp = (const float*)d_in[4];
    float* out = (float*)d_out;

    cudaFuncSetAttribute(qkv_gemm,  cudaFuncAttributeMaxDynamicSharedMemorySize, GEMM_SMEM);
    cudaFuncSetAttribute(proj_gemm, cudaFuncAttributeMaxDynamicSharedMemorySize, GEMM_SMEM);
    cudaFuncSetAttribute(attn_tc,   cudaFuncAttributeMaxDynamicSharedMemorySize, ATT_SMEM);

    conv_x<<<(B_ * T_ * E_) / 2048, 256>>>(x);
    tr_wqkv<<<dim3(E_ / 64, H_, 3), 256>>>(wq, wk, wv);
    tr_wp<<<dim3(E_ / 64, E_ / 64), 256>>>(wp);
    qkv_gemm<<<dim3((B_ * T_) / 128, (3 * NH) / 128), 128, GEMM_SMEM>>>();
    attn_tc<<<dim3(T_ / 128, H_, B_), 128, ATT_SMEM>>>();
    proj_gemm<<<dim3((B_ * T_) / 128, E_ / 128), 128, GEMM_SMEM>>>(out);
}